// round 1
// baseline (speedup 1.0000x reference)
#include <cuda_runtime.h>
#include <cuda_bf16.h>
#include <math.h>

#define BSZ 32
#define CCH 128
#define HH  32
#define WW  32
#define HW  1024
#define CHW 131072
#define MH  5
#define LAM 1e-4f
#define TOL 1e-5f

// ---------------- device state ----------------
__device__ float d_Fh[BSZ * MH * CHW];   // history of f outputs
__device__ float d_G [BSZ * MH * CHW];   // G = Fh - X (residual history)
__device__ float d_z [BSZ * CHW];        // current iterate (input to f)
__device__ float d_gram [BSZ * 25];      // per-batch 5x5 Gram
__device__ float d_alpha[BSZ * 5];
__device__ float d_partial[512 * 8];     // per f_eval block: 5 gram dots, rden
__device__ float d_Wt[CCH * 9 * CCH];    // weights transposed [ci][ky][kx][co]
__device__ int   d_flag;                 // converged flag

// ---------------- init ----------------
__global__ void init_kernel() {
    int idx = blockIdx.x * 256 + threadIdx.x;       // covers BSZ*MH*CHW/4
    float4 z = make_float4(0.f, 0.f, 0.f, 0.f);
    ((float4*)d_Fh)[idx] = z;
    ((float4*)d_G)[idx]  = z;
    if (idx < BSZ * CHW / 4) {
        const float c = 1.0f / 128.0f;
        ((float4*)d_z)[idx] = make_float4(c, c, c, c);
    }
    if (idx < BSZ * 25) d_gram[idx] = 0.f;
    if (idx == 0) d_flag = 0;
}

__global__ void transpose_w_kernel(const float* __restrict__ Wsrc) {
    int idx = blockIdx.x * 256 + threadIdx.x;       // over 128*128*9
    if (idx >= CCH * CCH * 9) return;
    int co = idx / (CCH * 9);
    int r  = idx - co * (CCH * 9);
    int ci = r / 9;
    int t  = r - ci * 9;                            // ky*3+kx
    d_Wt[(ci * 9 + t) * CCH + co] = Wsrc[idx];
}

// z = Fh[:,0,:]
__global__ void copy_z_kernel() {
    int idx = blockIdx.x * 256 + threadIdx.x;       // < BSZ*CHW/4
    int b  = idx >> 15;
    int l4 = idx & 32767;
    ((float4*)d_z)[idx] = ((const float4*)d_Fh)[(b * MH) * 32768 + l4];
}

// ---------------- f evaluation + fused Gram/residual partials ----------------
// grid (16 row-pairs, 32 batches), 256 threads, dyn smem 128*4*34 floats
__global__ __launch_bounds__(256, 2)
void f_eval_kernel(const float* __restrict__ x, const int* __restrict__ mask,
                   const float* __restrict__ bias, float* __restrict__ out,
                   int slot) {
    if (d_flag) return;
    extern __shared__ float sm[];
    const int tid = threadIdx.x;
    const int b   = blockIdx.y;
    const int h0  = blockIdx.x * 2;

    const float* zin = d_z + b * CHW;
    const float* xb  = x + b * CHW;
    const int*   mb  = mask + b * HW;

    // load zm tile: [ci 0..127][r 0..3][wi 0..33], r->h0-1+r, wi->w-1
    for (int i = tid; i < CCH * 4 * 34; i += 256) {
        int ci  = i / 136;
        int rem = i - ci * 136;
        int r   = rem / 34;
        int wi  = rem - r * 34;
        int h   = h0 - 1 + r;
        int w   = wi - 1;
        float v = 0.f;
        if (h >= 0 && h < HH && (unsigned)w < (unsigned)WW) {
            int sp  = h * WW + w;
            int off = ci * HW + sp;
            v = mb[sp] ? xb[off] : zin[off];
        }
        sm[i] = v;
    }
    __syncthreads();

    const int w   = tid & 31;
    const int cg  = tid >> 5;
    const int co0 = cg * 16;

    float acc0[16], acc1[16];
#pragma unroll
    for (int k = 0; k < 16; k++) { acc0[k] = 0.f; acc1[k] = 0.f; }

    const float* Wb = d_Wt + co0;
    for (int ci = 0; ci < CCH; ci++) {
        const float* smci = sm + ci * 136;
        const float* wci  = Wb + ci * (9 * CCH);
#pragma unroll
        for (int ky = 0; ky < 3; ky++) {
#pragma unroll
            for (int kx = 0; kx < 3; kx++) {
                const float4* wp = reinterpret_cast<const float4*>(wci + (ky * 3 + kx) * CCH);
                float wv[16];
                *(float4*)&wv[0]  = wp[0];
                *(float4*)&wv[4]  = wp[1];
                *(float4*)&wv[8]  = wp[2];
                *(float4*)&wv[12] = wp[3];
                float za = smci[ky * 34 + w + kx];
                float zb = smci[(ky + 1) * 34 + w + kx];
#pragma unroll
                for (int k = 0; k < 16; k++) {
                    acc0[k] += wv[k] * za;
                    acc1[k] += wv[k] * zb;
                }
            }
        }
    }
    __syncthreads();                 // tile no longer needed; reuse sm for reductions
    float* red = sm;

    const int sp0 = h0 * WW + w;
    const int sp1 = sp0 + WW;

    // pre = 0.1*z + 0.9*(conv + bias)
#pragma unroll
    for (int k = 0; k < 16; k++) {
        float bb  = bias[co0 + k];
        int   off = (co0 + k) * HW;
        acc0[k] = 0.1f * zin[off + sp0] + 0.9f * (acc0[k] + bb);
        acc1[k] = 0.1f * zin[off + sp1] + 0.9f * (acc1[k] + bb);
    }

    // softmax over 128 channels spread across 8 warps (same lane w)
    float mx0 = -3.4e38f, mx1 = -3.4e38f;
#pragma unroll
    for (int k = 0; k < 16; k++) { mx0 = fmaxf(mx0, acc0[k]); mx1 = fmaxf(mx1, acc1[k]); }
    red[w * 8 + cg]       = mx0;
    red[256 + w * 8 + cg] = mx1;
    __syncthreads();
    float gm0 = red[w * 8], gm1 = red[256 + w * 8];
#pragma unroll
    for (int j = 1; j < 8; j++) {
        gm0 = fmaxf(gm0, red[w * 8 + j]);
        gm1 = fmaxf(gm1, red[256 + w * 8 + j]);
    }
    float s0 = 0.f, s1 = 0.f;
#pragma unroll
    for (int k = 0; k < 16; k++) {
        acc0[k] = __expf(acc0[k] - gm0); s0 += acc0[k];
        acc1[k] = __expf(acc1[k] - gm1); s1 += acc1[k];
    }
    __syncthreads();
    red[w * 8 + cg]       = s0;
    red[256 + w * 8 + cg] = s1;
    __syncthreads();
    float t0 = 0.f, t1 = 0.f;
#pragma unroll
    for (int j = 0; j < 8; j++) { t0 += red[w * 8 + j]; t1 += red[256 + w * 8 + j]; }
    const float inv0 = 1.f / t0, inv1 = 1.f / t1;

    // write fnew, G_slot; accumulate gram-row + residual partials
    float pg[6] = {0.f, 0.f, 0.f, 0.f, 0.f, 0.f};
    float* Fs = d_Fh + (b * MH + slot) * CHW;
    float* Gs = d_G  + (b * MH + slot) * CHW;
    float* ob = out + (size_t)b * CHW;
#pragma unroll
    for (int k = 0; k < 16; k++) {
        int off = (co0 + k) * HW;
        {
            float f = acc0[k] * inv0;
            int o = off + sp0;
            Fs[o] = f; ob[o] = f;
            float g = f - zin[o];
            Gs[o] = g;
            pg[5] += f * f;
#pragma unroll
            for (int j = 0; j < 5; j++)
                pg[j] += g * ((j == slot) ? g : d_G[(b * MH + j) * CHW + o]);
        }
        {
            float f = acc1[k] * inv1;
            int o = off + sp1;
            Fs[o] = f; ob[o] = f;
            float g = f - zin[o];
            Gs[o] = g;
            pg[5] += f * f;
#pragma unroll
            for (int j = 0; j < 5; j++)
                pg[j] += g * ((j == slot) ? g : d_G[(b * MH + j) * CHW + o]);
        }
    }

    // deterministic block reduction of 6 partials
#pragma unroll
    for (int i = 0; i < 6; i++) {
        float v = pg[i];
#pragma unroll
        for (int o = 16; o > 0; o >>= 1) v += __shfl_down_sync(0xffffffffu, v, o);
        pg[i] = v;
    }
    __syncthreads();                 // sums in red all consumed above
    if ((tid & 31) == 0) {
        int wp = tid >> 5;
#pragma unroll
        for (int i = 0; i < 6; i++) red[wp * 6 + i] = pg[i];
    }
    __syncthreads();
    if (tid == 0) {
        int blk = b * 16 + blockIdx.x;
#pragma unroll
        for (int i = 0; i < 6; i++) {
            float s = 0.f;
#pragma unroll
            for (int wp = 0; wp < 8; wp++) s += red[wp * 6 + i];
            d_partial[blk * 8 + i] = s;
        }
    }
}

// ---------------- finalize partials: gram row/col + residual/flag ----------------
__global__ void reduce_kernel(int slot, int check) {
    if (d_flag) return;
    int b = threadIdx.x;             // 32 threads
    float s[6] = {0.f, 0.f, 0.f, 0.f, 0.f, 0.f};
    for (int blk = 0; blk < 16; blk++)
#pragma unroll
        for (int i = 0; i < 6; i++) s[i] += d_partial[(b * 16 + blk) * 8 + i];
#pragma unroll
    for (int j = 0; j < 5; j++) {
        d_gram[b * 25 + slot * 5 + j] = s[j];
        d_gram[b * 25 + j * 5 + slot] = s[j];
    }
    float rn = s[slot], rd = s[5];
#pragma unroll
    for (int o = 16; o > 0; o >>= 1) {
        rn += __shfl_down_sync(0xffffffffu, rn, o);
        rd += __shfl_down_sync(0xffffffffu, rd, o);
    }
    if (b == 0 && check) {
        float res = sqrtf(rn) / (1e-5f + sqrtf(rd));
        if (res < TOL) d_flag = 1;
    }
}

// ---------------- 6x6 masked Anderson solve (one thread per batch) ----------------
__global__ void solve_kernel(int n) {
    if (d_flag) return;
    int b = threadIdx.x;
    if (b >= BSZ) return;
    float A[6][7];
    A[0][0] = 0.f; A[0][6] = 1.f;
    for (int j = 0; j < 5; j++) {
        float aj = (j < n) ? 1.f : 0.f;
        A[0][j + 1] = aj;
        A[j + 1][0] = aj;
        A[j + 1][6] = 0.f;
    }
    for (int i = 0; i < 5; i++)
        for (int j = 0; j < 5; j++) {
            float v;
            if (i < n && j < n) v = d_gram[b * 25 + i * 5 + j] + ((i == j) ? LAM : 0.f);
            else v = (i == j) ? 1.f : 0.f;
            A[i + 1][j + 1] = v;
        }
    // Gaussian elimination with partial pivoting
    for (int col = 0; col < 6; col++) {
        int p = col; float best = fabsf(A[col][col]);
        for (int r = col + 1; r < 6; r++) {
            float v = fabsf(A[r][col]);
            if (v > best) { best = v; p = r; }
        }
        if (p != col)
            for (int c = 0; c < 7; c++) { float t = A[col][c]; A[col][c] = A[p][c]; A[p][c] = t; }
        float ip = 1.f / A[col][col];
        for (int r = col + 1; r < 6; r++) {
            float fac = A[r][col] * ip;
            for (int c = col; c < 7; c++) A[r][c] -= fac * A[col][c];
        }
    }
    float y[6];
    for (int r = 5; r >= 0; r--) {
        float v = A[r][6];
        for (int c = r + 1; c < 6; c++) v -= A[r][c] * y[c];
        y[r] = v / A[r][r];
    }
    for (int j = 0; j < 5; j++) d_alpha[b * 5 + j] = (j < n) ? y[j + 1] : 0.f;
}

// ---------------- xnew = sum_j alpha_j * Fh_j ----------------
__global__ void combine_kernel() {
    if (d_flag) return;
    int idx = blockIdx.x * 256 + threadIdx.x;       // < BSZ*CHW/4
    int b  = idx >> 15;
    int l4 = idx & 32767;
    const float* al = d_alpha + b * 5;
    float a0 = al[0], a1 = al[1], a2 = al[2], a3 = al[3], a4 = al[4];
    const float4* F = (const float4*)d_Fh;
    int base = b * MH * 32768 + l4;
    float4 f0 = F[base];
    float4 f1 = F[base + 32768];
    float4 f2 = F[base + 65536];
    float4 f3 = F[base + 98304];
    float4 f4 = F[base + 131072];
    float4 r;
    r.x = a0 * f0.x + a1 * f1.x + a2 * f2.x + a3 * f3.x + a4 * f4.x;
    r.y = a0 * f0.y + a1 * f1.y + a2 * f2.y + a3 * f3.y + a4 * f4.y;
    r.z = a0 * f0.z + a1 * f1.z + a2 * f2.z + a3 * f3.z + a4 * f4.z;
    r.w = a0 * f0.w + a1 * f1.w + a2 * f2.w + a3 * f3.w + a4 * f4.w;
    ((float4*)d_z)[idx] = r;
}

// ---------------- host ----------------
extern "C" void kernel_launch(void* const* d_in, const int* in_sizes, int n_in,
                              void* d_out, int out_size) {
    const float* x    = (const float*)d_in[0];
    const float* Wsrc = (const float*)d_in[1];
    const float* bias = (const float*)d_in[2];
    const int*   mask = (const int*)d_in[3];
    float*       out  = (float*)d_out;

    cudaFuncSetAttribute(f_eval_kernel, cudaFuncAttributeMaxDynamicSharedMemorySize, 70000);
    const size_t smem = CCH * 4 * 34 * sizeof(float);   // 69632
    const dim3 fgrid(16, BSZ);

    transpose_w_kernel<<<(CCH * CCH * 9 + 255) / 256, 256>>>(Wsrc);
    init_kernel<<<(BSZ * MH * CHW / 4) / 256, 256>>>();

    // F0 = f(z0)
    f_eval_kernel<<<fgrid, 256, smem>>>(x, mask, bias, out, 0);
    reduce_kernel<<<1, 32>>>(0, 0);
    // z = F0 ; F1 = f(F0)
    copy_z_kernel<<<(BSZ * CHW / 4) / 256, 256>>>();
    f_eval_kernel<<<fgrid, 256, smem>>>(x, mask, bias, out, 1);
    reduce_kernel<<<1, 32>>>(1, 0);

    for (int k = 2; k < 50; k++) {
        int n = (k < MH) ? k : MH;
        int slot = k % MH;
        solve_kernel<<<1, 32>>>(n);
        combine_kernel<<<(BSZ * CHW / 4) / 256, 256>>>();
        f_eval_kernel<<<fgrid, 256, smem>>>(x, mask, bias, out, slot);
        reduce_kernel<<<1, 32>>>(slot, 1);
    }
}

// round 2
// speedup vs baseline: 1.0136x; 1.0136x over previous
#include <cuda_runtime.h>
#include <cuda_bf16.h>
#include <math.h>

#define BSZ 32
#define CCH 128
#define HH  32
#define WW  32
#define HW  1024
#define CHW 131072
#define MH  5
#define LAM 1e-4f
#define TOL 1e-5f

typedef unsigned long long u64;

// ---------------- device state ----------------
__device__ float d_Fh[BSZ * MH * CHW];   // history of f outputs
__device__ float d_G [BSZ * MH * CHW];   // G = Fh - X (residual history)
__device__ float d_z [BSZ * CHW];        // current iterate (input to f)
__device__ float d_gram [BSZ * 25];      // per-batch 5x5 Gram
__device__ float d_alpha[BSZ * 5];
__device__ float d_partial[512 * 8];     // per f_eval block: 5 gram dots, rden
__device__ float d_Wt[CCH * 9 * CCH];    // weights transposed [ci][ky][kx][co]
__device__ int   d_flag;                 // converged flag

// ---------------- packed fp32x2 helpers ----------------
__device__ __forceinline__ u64 pack2(float v) {
    u64 r; asm("mov.b64 %0, {%1, %1};" : "=l"(r) : "f"(v)); return r;
}
__device__ __forceinline__ void fma2(u64& a, u64 b, u64 c) {
    asm("fma.rn.f32x2 %0, %1, %2, %0;" : "+l"(a) : "l"(b), "l"(c));
}
__device__ __forceinline__ float2 unpack2(u64 v) {
    float2 r; asm("mov.b64 {%0, %1}, %2;" : "=f"(r.x), "=f"(r.y) : "l"(v)); return r;
}

// ---------------- init ----------------
__global__ void init_kernel() {
    int idx = blockIdx.x * 256 + threadIdx.x;       // covers BSZ*MH*CHW/4
    float4 z = make_float4(0.f, 0.f, 0.f, 0.f);
    ((float4*)d_Fh)[idx] = z;
    ((float4*)d_G)[idx]  = z;
    if (idx < BSZ * CHW / 4) {
        const float c = 1.0f / 128.0f;
        ((float4*)d_z)[idx] = make_float4(c, c, c, c);
    }
    if (idx < BSZ * 25) d_gram[idx] = 0.f;
    if (idx == 0) d_flag = 0;
}

__global__ void transpose_w_kernel(const float* __restrict__ Wsrc) {
    int idx = blockIdx.x * 256 + threadIdx.x;       // over 128*128*9
    if (idx >= CCH * CCH * 9) return;
    int co = idx / (CCH * 9);
    int r  = idx - co * (CCH * 9);
    int ci = r / 9;
    int t  = r - ci * 9;                            // ky*3+kx
    d_Wt[(ci * 9 + t) * CCH + co] = Wsrc[idx];
}

// z = Fh[:,0,:]
__global__ void copy_z_kernel() {
    int idx = blockIdx.x * 256 + threadIdx.x;       // < BSZ*CHW/4
    int b  = idx >> 15;
    int l4 = idx & 32767;
    ((float4*)d_z)[idx] = ((const float4*)d_Fh)[(b * MH) * 32768 + l4];
}

// ---------------- f evaluation + fused Gram/residual partials ----------------
// grid (16 row-pairs, 32 batches), 256 threads, dyn smem 128*4*34 floats
__global__ __launch_bounds__(256, 2)
void f_eval_kernel(const float* __restrict__ x, const int* __restrict__ mask,
                   const float* __restrict__ bias, float* __restrict__ out,
                   int slot) {
    if (d_flag) return;
    extern __shared__ float sm[];
    const int tid = threadIdx.x;
    const int b   = blockIdx.y;
    const int h0  = blockIdx.x * 2;

    const float* zin = d_z + b * CHW;
    const float* xb  = x + b * CHW;
    const int*   mb  = mask + b * HW;

    // load zm tile: [ci 0..127][r 0..3][wi 0..33], r->h0-1+r, wi->w-1
    for (int i = tid; i < CCH * 4 * 34; i += 256) {
        int ci  = i / 136;
        int rem = i - ci * 136;
        int r   = rem / 34;
        int wi  = rem - r * 34;
        int h   = h0 - 1 + r;
        int w   = wi - 1;
        float v = 0.f;
        if (h >= 0 && h < HH && (unsigned)w < (unsigned)WW) {
            int sp  = h * WW + w;
            int off = ci * HW + sp;
            v = mb[sp] ? xb[off] : zin[off];
        }
        sm[i] = v;
    }
    __syncthreads();

    const int w   = tid & 31;
    const int cg  = tid >> 5;
    const int co0 = cg * 16;

    // packed accumulators: 8 pairs per row = 16 output channels
    u64 acc0[8], acc1[8];
#pragma unroll
    for (int k = 0; k < 8; k++) { acc0[k] = 0ull; acc1[k] = 0ull; }

    const float* Wb = d_Wt + co0;
    for (int ci = 0; ci < CCH; ci++) {
        const float* smci = sm + ci * 136;
        const float* wci  = Wb + ci * (9 * CCH);
#pragma unroll
        for (int t = 0; t < 9; t++) {
            const int ky = t / 3, kx = t % 3;
            const ulonglong2* wp = reinterpret_cast<const ulonglong2*>(wci + t * CCH);
            ulonglong2 wA = wp[0];   // co 0..3 (2 pairs)
            ulonglong2 wB = wp[1];   // co 4..7
            ulonglong2 wC = wp[2];   // co 8..11
            ulonglong2 wD = wp[3];   // co 12..15
            u64 za2 = pack2(smci[ky * 34 + w + kx]);
            u64 zb2 = pack2(smci[(ky + 1) * 34 + w + kx]);
            fma2(acc0[0], wA.x, za2); fma2(acc0[1], wA.y, za2);
            fma2(acc0[2], wB.x, za2); fma2(acc0[3], wB.y, za2);
            fma2(acc0[4], wC.x, za2); fma2(acc0[5], wC.y, za2);
            fma2(acc0[6], wD.x, za2); fma2(acc0[7], wD.y, za2);
            fma2(acc1[0], wA.x, zb2); fma2(acc1[1], wA.y, zb2);
            fma2(acc1[2], wB.x, zb2); fma2(acc1[3], wB.y, zb2);
            fma2(acc1[4], wC.x, zb2); fma2(acc1[5], wC.y, zb2);
            fma2(acc1[6], wD.x, zb2); fma2(acc1[7], wD.y, zb2);
        }
    }
    __syncthreads();                 // tile no longer needed; reuse sm for reductions
    float* red = sm;

    // unpack to scalar accumulators
    float a0[16], a1[16];
#pragma unroll
    for (int p = 0; p < 8; p++) {
        float2 f0 = unpack2(acc0[p]); a0[2 * p] = f0.x; a0[2 * p + 1] = f0.y;
        float2 f1 = unpack2(acc1[p]); a1[2 * p] = f1.x; a1[2 * p + 1] = f1.y;
    }

    const int sp0 = h0 * WW + w;
    const int sp1 = sp0 + WW;

    // pre = 0.1*z + 0.9*(conv + bias)
#pragma unroll
    for (int k = 0; k < 16; k++) {
        float bb  = bias[co0 + k];
        int   off = (co0 + k) * HW;
        a0[k] = 0.1f * zin[off + sp0] + 0.9f * (a0[k] + bb);
        a1[k] = 0.1f * zin[off + sp1] + 0.9f * (a1[k] + bb);
    }

    // softmax over 128 channels spread across 8 warps (same lane w)
    float mx0 = -3.4e38f, mx1 = -3.4e38f;
#pragma unroll
    for (int k = 0; k < 16; k++) { mx0 = fmaxf(mx0, a0[k]); mx1 = fmaxf(mx1, a1[k]); }
    red[w * 8 + cg]       = mx0;
    red[256 + w * 8 + cg] = mx1;
    __syncthreads();
    float gm0 = red[w * 8], gm1 = red[256 + w * 8];
#pragma unroll
    for (int j = 1; j < 8; j++) {
        gm0 = fmaxf(gm0, red[w * 8 + j]);
        gm1 = fmaxf(gm1, red[256 + w * 8 + j]);
    }
    float s0 = 0.f, s1 = 0.f;
#pragma unroll
    for (int k = 0; k < 16; k++) {
        a0[k] = __expf(a0[k] - gm0); s0 += a0[k];
        a1[k] = __expf(a1[k] - gm1); s1 += a1[k];
    }
    __syncthreads();
    red[w * 8 + cg]       = s0;
    red[256 + w * 8 + cg] = s1;
    __syncthreads();
    float t0 = 0.f, t1 = 0.f;
#pragma unroll
    for (int j = 0; j < 8; j++) { t0 += red[w * 8 + j]; t1 += red[256 + w * 8 + j]; }
    const float inv0 = 1.f / t0, inv1 = 1.f / t1;

    // write fnew, G_slot; accumulate gram-row + residual partials
    float pg[6] = {0.f, 0.f, 0.f, 0.f, 0.f, 0.f};
    float* Fs = d_Fh + (b * MH + slot) * CHW;
    float* Gs = d_G  + (b * MH + slot) * CHW;
    float* ob = out + (size_t)b * CHW;
#pragma unroll
    for (int k = 0; k < 16; k++) {
        int off = (co0 + k) * HW;
        {
            float f = a0[k] * inv0;
            int o = off + sp0;
            Fs[o] = f; ob[o] = f;
            float g = f - zin[o];
            Gs[o] = g;
            pg[5] += f * f;
#pragma unroll
            for (int j = 0; j < 5; j++)
                pg[j] += g * ((j == slot) ? g : d_G[(b * MH + j) * CHW + o]);
        }
        {
            float f = a1[k] * inv1;
            int o = off + sp1;
            Fs[o] = f; ob[o] = f;
            float g = f - zin[o];
            Gs[o] = g;
            pg[5] += f * f;
#pragma unroll
            for (int j = 0; j < 5; j++)
                pg[j] += g * ((j == slot) ? g : d_G[(b * MH + j) * CHW + o]);
        }
    }

    // deterministic block reduction of 6 partials
#pragma unroll
    for (int i = 0; i < 6; i++) {
        float v = pg[i];
#pragma unroll
        for (int o = 16; o > 0; o >>= 1) v += __shfl_down_sync(0xffffffffu, v, o);
        pg[i] = v;
    }
    __syncthreads();                 // sums in red all consumed above
    if ((tid & 31) == 0) {
        int wp = tid >> 5;
#pragma unroll
        for (int i = 0; i < 6; i++) red[wp * 6 + i] = pg[i];
    }
    __syncthreads();
    if (tid == 0) {
        int blk = b * 16 + blockIdx.x;
#pragma unroll
        for (int i = 0; i < 6; i++) {
            float s = 0.f;
#pragma unroll
            for (int wp = 0; wp < 8; wp++) s += red[wp * 6 + i];
            d_partial[blk * 8 + i] = s;
        }
    }
}

// ---------------- reduce partials -> gram/flag, then solve next alpha ----------------
__global__ void reduce_solve_kernel(int slot, int check, int n_next) {
    if (d_flag) return;
    int b = threadIdx.x;             // 32 threads, lane == batch
    float s[6] = {0.f, 0.f, 0.f, 0.f, 0.f, 0.f};
    for (int blk = 0; blk < 16; blk++)
#pragma unroll
        for (int i = 0; i < 6; i++) s[i] += d_partial[(b * 16 + blk) * 8 + i];
#pragma unroll
    for (int j = 0; j < 5; j++) {
        d_gram[b * 25 + slot * 5 + j] = s[j];
        d_gram[b * 25 + j * 5 + slot] = s[j];
    }
    float rn = s[slot], rd = s[5];
#pragma unroll
    for (int o = 16; o > 0; o >>= 1) {
        rn += __shfl_down_sync(0xffffffffu, rn, o);
        rd += __shfl_down_sync(0xffffffffu, rd, o);
    }
    if (b == 0 && check) {
        float res = sqrtf(rn) / (1e-5f + sqrtf(rd));
        if (res < TOL) d_flag = 1;
    }

    // ---- solve for next iteration's alpha (each lane = its batch) ----
    const int n = n_next;
    float A[6][7];
    A[0][0] = 0.f; A[0][6] = 1.f;
    for (int j = 0; j < 5; j++) {
        float aj = (j < n) ? 1.f : 0.f;
        A[0][j + 1] = aj;
        A[j + 1][0] = aj;
        A[j + 1][6] = 0.f;
    }
    for (int i = 0; i < 5; i++)
        for (int j = 0; j < 5; j++) {
            float v;
            if (i < n && j < n) v = d_gram[b * 25 + i * 5 + j] + ((i == j) ? LAM : 0.f);
            else v = (i == j) ? 1.f : 0.f;
            A[i + 1][j + 1] = v;
        }
    for (int col = 0; col < 6; col++) {
        int p = col; float best = fabsf(A[col][col]);
        for (int r = col + 1; r < 6; r++) {
            float v = fabsf(A[r][col]);
            if (v > best) { best = v; p = r; }
        }
        if (p != col)
            for (int c = 0; c < 7; c++) { float t = A[col][c]; A[col][c] = A[p][c]; A[p][c] = t; }
        float ip = 1.f / A[col][col];
        for (int r = col + 1; r < 6; r++) {
            float fac = A[r][col] * ip;
            for (int c = col; c < 7; c++) A[r][c] -= fac * A[col][c];
        }
    }
    float y[6];
    for (int r = 5; r >= 0; r--) {
        float v = A[r][6];
        for (int c = r + 1; c < 6; c++) v -= A[r][c] * y[c];
        y[r] = v / A[r][r];
    }
    for (int j = 0; j < 5; j++) d_alpha[b * 5 + j] = (j < n) ? y[j + 1] : 0.f;
}

// ---------------- xnew = sum_j alpha_j * Fh_j ----------------
__global__ void combine_kernel() {
    if (d_flag) return;
    int idx = blockIdx.x * 256 + threadIdx.x;       // < BSZ*CHW/4
    int b  = idx >> 15;
    int l4 = idx & 32767;
    const float* al = d_alpha + b * 5;
    float a0 = al[0], a1 = al[1], a2 = al[2], a3 = al[3], a4 = al[4];
    const float4* F = (const float4*)d_Fh;
    int base = b * MH * 32768 + l4;
    float4 f0 = F[base];
    float4 f1 = F[base + 32768];
    float4 f2 = F[base + 65536];
    float4 f3 = F[base + 98304];
    float4 f4 = F[base + 131072];
    float4 r;
    r.x = a0 * f0.x + a1 * f1.x + a2 * f2.x + a3 * f3.x + a4 * f4.x;
    r.y = a0 * f0.y + a1 * f1.y + a2 * f2.y + a3 * f3.y + a4 * f4.y;
    r.z = a0 * f0.z + a1 * f1.z + a2 * f2.z + a3 * f3.z + a4 * f4.z;
    r.w = a0 * f0.w + a1 * f1.w + a2 * f2.w + a3 * f3.w + a4 * f4.w;
    ((float4*)d_z)[idx] = r;
}

// ---------------- host ----------------
extern "C" void kernel_launch(void* const* d_in, const int* in_sizes, int n_in,
                              void* d_out, int out_size) {
    const float* x    = (const float*)d_in[0];
    const float* Wsrc = (const float*)d_in[1];
    const float* bias = (const float*)d_in[2];
    const int*   mask = (const int*)d_in[3];
    float*       out  = (float*)d_out;

    cudaFuncSetAttribute(f_eval_kernel, cudaFuncAttributeMaxDynamicSharedMemorySize, 70000);
    const size_t smem = CCH * 4 * 34 * sizeof(float);   // 69632
    const dim3 fgrid(16, BSZ);

    transpose_w_kernel<<<(CCH * CCH * 9 + 255) / 256, 256>>>(Wsrc);
    init_kernel<<<(BSZ * MH * CHW / 4) / 256, 256>>>();

    // F0 = f(z0)
    f_eval_kernel<<<fgrid, 256, smem>>>(x, mask, bias, out, 0);
    reduce_solve_kernel<<<1, 32>>>(0, 0, 2);   // gram row 0; solve unused until k=2
    // z = F0 ; F1 = f(F0)
    copy_z_kernel<<<(BSZ * CHW / 4) / 256, 256>>>();
    f_eval_kernel<<<fgrid, 256, smem>>>(x, mask, bias, out, 1);
    reduce_solve_kernel<<<1, 32>>>(1, 0, 2);   // solve for k=2 (n=2)

    for (int k = 2; k < 50; k++) {
        int slot = k % MH;
        int n_next = ((k + 1) < MH) ? (k + 1) : MH;
        combine_kernel<<<(BSZ * CHW / 4) / 256, 256>>>();
        f_eval_kernel<<<fgrid, 256, smem>>>(x, mask, bias, out, slot);
        reduce_solve_kernel<<<1, 32>>>(slot, 1, n_next);
    }
}